// round 5
// baseline (speedup 1.0000x reference)
#include <cuda_runtime.h>
#include <cuda_bf16.h>

#define N_NODES 4096
#define DIM     8
#define NE      131072
#define NH1     16
#define NH2     16
#define NOUT    112
#define TOPK    16
#define CAP     128
#define NB      148
#define TPB     256
#define STRIDE  (NB * TPB)

// ---------------- scratch ----------------
__device__ int           g_is64;
__device__ float         g_ev[NE];
__device__ int           g_row_cnt[N_NODES];
__device__ int           g_cols[N_NODES * CAP];
__device__ int           g_eids[N_NODES * CAP];
__device__ int           g_pairs[NE];
__device__ int           g_npairs;
__device__ float         g_deg[N_NODES];
__device__ float         g_dinv[N_NODES];
__device__ float         g_xwnbr[N_NODES];
__device__ float         g_hw1[N_NODES * NH1];
__device__ float         g_agg1[N_NODES * NH1];
__device__ float         g_hw2[N_NODES * NH2];
__device__ float         g_agg2[N_NODES * NH2];

// grid barrier state (zero-init; gen monotonically increases across replays)
__device__ unsigned int  g_bar_cnt;
__device__ unsigned int  g_bar_gen;

__device__ __forceinline__ void grid_barrier() {
    __syncthreads();
    if (threadIdx.x == 0) {
        __threadfence();
        unsigned gen = atomicAdd(&g_bar_gen, 0u);   // read before arriving: safe,
        // release for this phase needs OUR arrival, so gen can't bump in between.
        unsigned arrived = atomicAdd(&g_bar_cnt, 1u);
        if (arrived == NB - 1) {
            g_bar_cnt = 0;
            __threadfence();
            atomicAdd(&g_bar_gen, 1u);
        } else {
            while (atomicAdd(&g_bar_gen, 0u) == gen) { }
        }
    }
    __syncthreads();
}

__device__ __forceinline__ int e_row(const void* ei, int e) {
    if (g_is64) return (int)((const long long*)ei)[e];
    return ((const int*)ei)[e];
}
__device__ __forceinline__ int e_col(const void* ei, int e) {
    if (g_is64) return (int)((const long long*)ei)[NE + e];
    return ((const int*)ei)[NE + e];
}

// ---------------- single fused persistent kernel ----------------
__global__ void __launch_bounds__(TPB, 1)
k_fused(const void*  __restrict__ ei,
        const float* __restrict__ edge_attr,
        const float* __restrict__ x,
        const int*   __restrict__ node_mask,
        const float* __restrict__ mlp_w,
        const float* __restrict__ w1,
        const float* __restrict__ b1,
        const float* __restrict__ w2,
        const float* __restrict__ b2,
        const float* __restrict__ fc_w,
        const float* __restrict__ fc_b,
        float*       __restrict__ out) {
    const int tid  = blockIdx.x * TPB + threadIdx.x;
    const int w    = threadIdx.x >> 5;
    const int lane = threadIdx.x & 31;

    __shared__ int           s_col[8][CAP];
    __shared__ int           s_eid[8][CAP];
    __shared__ float         s_key[8][CAP];
    __shared__ unsigned char s_rep[8][CAP];

    // ---- phase 0: dtype probe, per-edge ev, per-node init ----
    if (blockIdx.x == 0 && w == 0) {   // warp 0 of block 0: probe
        const int* raw = (const int*)ei;
        int nz = 0;
        for (int i = lane; i < 1024; i += 32)
            if (raw[2 * i + 1] != 0) nz = 1;
        unsigned m = __ballot_sync(0xffffffffu, nz);
        if (lane == 0) { g_is64 = (m == 0) ? 1 : 0; g_npairs = 0; }
    }
    {
        float we[DIM], wn[DIM];
#pragma unroll
        for (int d = 0; d < DIM; d++) { we[d] = mlp_w[2 * DIM + d]; wn[d] = mlp_w[DIM + d]; }
        for (int e = tid; e < NE; e += STRIDE) {
            const float4* ea = (const float4*)(edge_attr + e * DIM);
            float4 a0 = ea[0], a1 = ea[1];
            g_ev[e] = a0.x * we[0] + a0.y * we[1] + a0.z * we[2] + a0.w * we[3]
                    + a1.x * we[4] + a1.y * we[5] + a1.z * we[6] + a1.w * we[7];
        }
        for (int n = tid; n < N_NODES; n += STRIDE) {
            g_row_cnt[n] = 0;
            g_deg[n] = 1.0f;
            const float4* xr = (const float4*)(x + n * DIM);
            float4 x0 = xr[0], x1 = xr[1];
            g_xwnbr[n] = x0.x * wn[0] + x0.y * wn[1] + x0.z * wn[2] + x0.w * wn[3]
                       + x1.x * wn[4] + x1.y * wn[5] + x1.z * wn[6] + x1.w * wn[7];
        }
    }
    grid_barrier();

    // ---- phase 1: bucket scatter ----
    for (int e = tid; e < NE; e += STRIDE) {
        int r = e_row(ei, e);
        int c = e_col(ei, e);
        if ((unsigned)r >= N_NODES || (unsigned)c >= N_NODES) continue;
        int p = atomicAdd(&g_row_cnt[r], 1);
        if (p < CAP) {
            g_cols[r * CAP + p] = c;
            g_eids[r * CAP + p] = e;
        }
    }
    grid_barrier();

    // ---- phase 2: top-K per row (one warp per row) ----
    {
        int warp_global = blockIdx.x * 8 + w;
        for (int r = warp_global; r < N_NODES; r += NB * 8) {
            int base = r * CAP;
            int d = g_row_cnt[r]; if (d > CAP) d = CAP;
            for (int i = lane; i < d; i += 32) {
                s_col[w][i] = g_cols[base + i];
                s_eid[w][i] = g_eids[base + i];
            }
            __syncwarp();
            int myrep = 0;
            for (int i = lane; i < d; i += 32) {
                int ci = s_col[w][i];
                int ei_i = s_eid[w][i];
                int best = ei_i;
                for (int j = 0; j < d; j++)
                    if (s_col[w][j] == ci && s_eid[w][j] > best) best = s_eid[w][j];
                unsigned char rp = (best == ei_i) ? 1 : 0;
                s_rep[w][i] = rp;
                s_key[w][i] = g_xwnbr[ci] + g_ev[best];
                myrep += rp;
            }
            __syncwarp();
            int nd = __reduce_add_sync(0xffffffffu, myrep);
            bool rowOK = (node_mask[r] != 0) && (nd >= TOPK);
            if (rowOK) {
                for (int i = lane; i < d; i += 32) {
                    float si = s_key[w][i];
                    int   ci = s_col[w][i];
                    int cnt = 0;
                    for (int j = 0; j < d; j++) {
                        if (s_rep[w][j]) {
                            float sj = s_key[w][j];
                            if (sj > si || (sj == si && s_col[w][j] < ci)) cnt++;
                        }
                    }
                    if (cnt < TOPK) {
                        int p = atomicAdd(&g_npairs, 1);
                        g_pairs[p] = (r << 12) | ci;
                        atomicAdd(&g_deg[ci], 1.0f);
                    }
                }
            }
            __syncwarp();
        }
    }
    grid_barrier();

    // ---- phase 3: dinv, hW1, agg1 init ----
    for (int n = tid; n < N_NODES; n += STRIDE) {
        float di = rsqrtf(g_deg[n]);
        g_dinv[n] = di;
        float xv[DIM];
        const float4* xr = (const float4*)(x + n * DIM);
        float4 x0 = xr[0], x1 = xr[1];
        xv[0]=x0.x; xv[1]=x0.y; xv[2]=x0.z; xv[3]=x0.w;
        xv[4]=x1.x; xv[5]=x1.y; xv[6]=x1.z; xv[7]=x1.w;
#pragma unroll
        for (int j = 0; j < NH1; j++) {
            float s = 0.f;
#pragma unroll
            for (int d = 0; d < DIM; d++) s += xv[d] * w1[d * NH1 + j];
            g_hw1[n * NH1 + j]  = s;
            g_agg1[n * NH1 + j] = di * di * s + b1[j];
        }
    }
    grid_barrier();

    // ---- phase 4: sparse aggregation layer 1 ----
    {
        int np = g_npairs;
        for (int e = tid; e < np; e += STRIDE) {
            int p = g_pairs[e];
            int r = p >> 12, c = p & 4095;
            float coef = g_dinv[r] * g_dinv[c];
#pragma unroll
            for (int j = 0; j < NH1; j++)
                atomicAdd(&g_agg1[c * NH1 + j], coef * g_hw1[r * NH1 + j]);
        }
    }
    grid_barrier();

    // ---- phase 5: relu, hW2, agg2 init ----
    for (int n = tid; n < N_NODES; n += STRIDE) {
        float di = g_dinv[n];
        float h[NH1];
#pragma unroll
        for (int j = 0; j < NH1; j++) h[j] = fmaxf(g_agg1[n * NH1 + j], 0.f);
#pragma unroll
        for (int j = 0; j < NH2; j++) {
            float s = 0.f;
#pragma unroll
            for (int k = 0; k < NH1; k++) s += h[k] * w2[k * NH2 + j];
            g_hw2[n * NH2 + j]  = s;
            g_agg2[n * NH2 + j] = di * di * s + b2[j];
        }
    }
    grid_barrier();

    // ---- phase 6: sparse aggregation layer 2 ----
    {
        int np = g_npairs;
        for (int e = tid; e < np; e += STRIDE) {
            int p = g_pairs[e];
            int r = p >> 12, c = p & 4095;
            float coef = g_dinv[r] * g_dinv[c];
#pragma unroll
            for (int j = 0; j < NH2; j++)
                atomicAdd(&g_agg2[c * NH2 + j], coef * g_hw2[r * NH2 + j]);
        }
    }
    grid_barrier();

    // ---- phase 7: fused relu + fc ----
    for (int idx = tid; idx < N_NODES * NOUT; idx += STRIDE) {
        int n = idx / NOUT;
        int o = idx - n * NOUT;
        float s = fc_b[o];
#pragma unroll
        for (int j = 0; j < NH2; j++)
            s += fmaxf(g_agg2[n * NH2 + j], 0.f) * fc_w[j * NOUT + o];
        out[idx] = s;
    }
}

// ---------------- launch ----------------
extern "C" void kernel_launch(void* const* d_in, const int* in_sizes, int n_in,
                              void* d_out, int out_size) {
    int s = (in_sizes[0] <= 1) ? 0 : -1;
    const void*  ei        = d_in[1 + s];
    const float* edge_attr = (const float*)d_in[2 + s];
    const float* x         = (const float*)d_in[3 + s];
    const int*   node_mask = (const int*)d_in[4 + s];
    const float* mlp_w     = (const float*)d_in[5 + s];
    const float* w1        = (const float*)d_in[7 + s];
    const float* b1        = (const float*)d_in[8 + s];
    const float* w2        = (const float*)d_in[9 + s];
    const float* b2        = (const float*)d_in[10 + s];
    const float* fc_w      = (const float*)d_in[11 + s];
    const float* fc_b      = (const float*)d_in[12 + s];
    float*       out       = (float*)d_out;

    k_fused<<<NB, TPB>>>(ei, edge_attr, x, node_mask, mlp_w,
                         w1, b1, w2, b2, fc_w, fc_b, out);
}

// round 8
// speedup vs baseline: 1.8964x; 1.8964x over previous
#include <cuda_runtime.h>
#include <cuda_bf16.h>

#define N_NODES 4096
#define DIM     8
#define NE      131072
#define NH1     16
#define NH2     16
#define NOUT    112
#define TOPK    16
#define CAP     128

// ---------------- scratch (zero-init at load; invariants restored each call) ----
__device__ float         g_ev[NE];
__device__ int           g_row_cnt[N_NODES];        // zeroed by k_out
__device__ int           g_cols[N_NODES * CAP];
__device__ int           g_eids[N_NODES * CAP];
__device__ int           g_pairs[NE];               // kept pairs incl. duplicate edges
__device__ int           g_npairs;                  // zeroed by k_out
__device__ float         g_degc[N_NODES];           // extra degree (deg-1); zeroed by k_pre
__device__ float         g_xwnbr[N_NODES];
__device__ float         g_hw1[N_NODES * NH1];
__device__ float         g_agg1[N_NODES * NH1];     // zeroed by k_out
__device__ float         g_hw2[N_NODES * NH2];
__device__ float         g_agg2[N_NODES * NH2];     // zeroed by k_pre

// ---------------- K1: probe + per-edge (ev, scatter) + per-node (xwnbr, hw1) ----
__global__ void k_pre(const void*  __restrict__ ei,
                      const float* __restrict__ edge_attr,
                      const float* __restrict__ x,
                      const float* __restrict__ mlp_w,
                      const float* __restrict__ w1) {
    __shared__ int s_is64;
    // per-block dtype probe (cheap L2 hits): int64 indices <4096 => high words 0
    if (threadIdx.x < 32) {
        const int* raw = (const int*)ei;
        int nz = 0;
        for (int i = threadIdx.x; i < 1024; i += 32)
            if (raw[2 * i + 1] != 0) nz = 1;
        unsigned m = __ballot_sync(0xffffffffu, nz);
        if (threadIdx.x == 0) s_is64 = (m == 0) ? 1 : 0;
    }
    __syncthreads();
    const int is64 = s_is64;
    const int t = blockIdx.x * blockDim.x + threadIdx.x;

    // ---- edge work: ev + bucket scatter ----
    if (t < NE) {
        const float4* ea = (const float4*)(edge_attr + t * DIM);
        float4 a0 = ea[0], a1 = ea[1];
        g_ev[t] = a0.x * mlp_w[16] + a0.y * mlp_w[17] + a0.z * mlp_w[18] + a0.w * mlp_w[19]
                + a1.x * mlp_w[20] + a1.y * mlp_w[21] + a1.z * mlp_w[22] + a1.w * mlp_w[23];
        int r, c;
        if (is64) {
            r = (int)((const long long*)ei)[t];
            c = (int)((const long long*)ei)[NE + t];
        } else {
            r = ((const int*)ei)[t];
            c = ((const int*)ei)[NE + t];
        }
        if ((unsigned)r < N_NODES && (unsigned)c < N_NODES) {
            int p = atomicAdd(&g_row_cnt[r], 1);
            if (p < CAP) {
                g_cols[r * CAP + p] = c;
                g_eids[r * CAP + p] = t;
            }
        }
    }
    // ---- node work: xwnbr ----
    if (t < N_NODES) {
        const float4* xr = (const float4*)(x + t * DIM);
        float4 x0 = xr[0], x1 = xr[1];
        g_xwnbr[t] = x0.x * mlp_w[8]  + x0.y * mlp_w[9]  + x0.z * mlp_w[10] + x0.w * mlp_w[11]
                   + x1.x * mlp_w[12] + x1.y * mlp_w[13] + x1.z * mlp_w[14] + x1.w * mlp_w[15];
    }
    // ---- hw1 = x @ w1, thread per (n, j) ----
    if (t < N_NODES * NH1) {
        int n = t >> 4, j = t & 15;
        const float* xr = x + n * DIM;
        float s = 0.f;
#pragma unroll
        for (int d = 0; d < DIM; d++) s += xr[d] * w1[d * NH1 + j];
        g_hw1[t] = s;
    }
    // ---- zero agg2 + degc (first touched two kernels later) ----
    if (t < N_NODES * NH2) g_agg2[t] = 0.f;
    if (t >= N_NODES * NH2 && t < N_NODES * NH2 + N_NODES) g_degc[t - N_NODES * NH2] = 0.f;
}

// ---------------- K2: top-K per row (one warp per row, shared staging) -------
__global__ void k_topk(const int* __restrict__ node_mask) {
    __shared__ int           s_col[8][CAP];
    __shared__ int           s_eid[8][CAP];
    __shared__ float         s_key[8][CAP];
    __shared__ unsigned char s_rep[8][CAP];

    int w    = threadIdx.x >> 5;
    int lane = threadIdx.x & 31;
    int r    = blockIdx.x * 8 + w;
    if (r >= N_NODES) return;
    int base = r * CAP;
    int d = g_row_cnt[r]; if (d > CAP) d = CAP;

    for (int i = lane; i < d; i += 32) {
        s_col[w][i] = g_cols[base + i];
        s_eid[w][i] = g_eids[base + i];
    }
    __syncwarp();

    int myrep = 0;
    for (int i = lane; i < d; i += 32) {
        int ci = s_col[w][i];
        int ei_i = s_eid[w][i];
        int best = ei_i;
        for (int j = 0; j < d; j++)
            if (s_col[w][j] == ci && s_eid[w][j] > best) best = s_eid[w][j];
        unsigned char rp = (best == ei_i) ? 1 : 0;
        s_rep[w][i] = rp;
        s_key[w][i] = g_xwnbr[ci] + g_ev[best];
        myrep += rp;
    }
    __syncwarp();
    int nd = __reduce_add_sync(0xffffffffu, myrep);
    bool rowOK = (node_mask[r] != 0) && (nd >= TOPK);

    // pass 2 over ALL entries (duplicate edges of kept columns are kept too)
    if (rowOK) {
        for (int i = lane; i < d; i += 32) {
            float si = s_key[w][i];
            int   ci = s_col[w][i];
            int cnt = 0;
            for (int j = 0; j < d; j++) {
                if (s_rep[w][j]) {
                    float sj = s_key[w][j];
                    if (sj > si || (sj == si && s_col[w][j] < ci)) cnt++;
                }
            }
            if (cnt < TOPK) {
                int p = atomicAdd(&g_npairs, 1);
                if (p < NE) g_pairs[p] = (r << 12) | ci;
                atomicAdd(&g_degc[ci], 1.0f);
            }
        }
    }
}

// ---------------- K3: sparse aggregation layer 1 (zero-based accumulate) -----
__global__ void k_agg1() {
    int e = blockIdx.x * blockDim.x + threadIdx.x;
    if (e >= g_npairs) return;
    int p = g_pairs[e];
    int r = p >> 12, c = p & 4095;
    float coef = rsqrtf(g_degc[r] + 1.0f) * rsqrtf(g_degc[c] + 1.0f);
#pragma unroll
    for (int j = 0; j < NH1; j++)
        atomicAdd(&g_agg1[c * NH1 + j], coef * g_hw1[r * NH1 + j]);
}

// ---------------- K4: h1 = relu(agg1 + di2*hw1 + b1); hw2 = h1@w2 ------------
__global__ void k_node2(const float* __restrict__ b1,
                        const float* __restrict__ w2) {
    int t = blockIdx.x * blockDim.x + threadIdx.x;
    if (t >= N_NODES * NH2) return;
    int n = t >> 4, j = t & 15;
    float di  = rsqrtf(g_degc[n] + 1.0f);
    float di2 = di * di;
    float s = 0.f;
#pragma unroll
    for (int k = 0; k < NH1; k++) {
        float h = fmaxf(g_agg1[n * NH1 + k] + di2 * g_hw1[n * NH1 + k] + b1[k], 0.f);
        s += h * w2[k * NH2 + j];
    }
    g_hw2[t] = s;
}

// ---------------- K5: sparse aggregation layer 2 -----------------------------
__global__ void k_agg2() {
    int e = blockIdx.x * blockDim.x + threadIdx.x;
    if (e >= g_npairs) return;
    int p = g_pairs[e];
    int r = p >> 12, c = p & 4095;
    float coef = rsqrtf(g_degc[r] + 1.0f) * rsqrtf(g_degc[c] + 1.0f);
#pragma unroll
    for (int j = 0; j < NH2; j++)
        atomicAdd(&g_agg2[c * NH2 + j], coef * g_hw2[r * NH2 + j]);
}

// ---------------- K6: out = relu(agg2 + di2*hw2 + b2) @ fc + cleanup ---------
__global__ void k_out(const float* __restrict__ b2,
                      const float* __restrict__ fc_w,
                      const float* __restrict__ fc_b,
                      float* __restrict__ out) {
    int idx = blockIdx.x * blockDim.x + threadIdx.x;
    if (idx < N_NODES * NOUT) {
        int n = idx / NOUT;
        int o = idx - n * NOUT;
        float di  = rsqrtf(g_degc[n] + 1.0f);
        float di2 = di * di;
        float s = fc_b[o];
#pragma unroll
        for (int k = 0; k < NH2; k++) {
            float h = fmaxf(g_agg2[n * NH2 + k] + di2 * g_hw2[n * NH2 + k] + b2[k], 0.f);
            s += h * fc_w[k * NOUT + o];
        }
        out[idx] = s;
    }
    // cleanup for next invocation (none of these are read by k_out)
    if (idx < N_NODES * NH1) g_agg1[idx] = 0.f;
    if (idx >= N_NODES * NH1 && idx < N_NODES * NH1 + N_NODES) g_row_cnt[idx - N_NODES * NH1] = 0;
    if (idx == N_NODES * NH1 + N_NODES) g_npairs = 0;
}

// ---------------- launch ----------------
extern "C" void kernel_launch(void* const* d_in, const int* in_sizes, int n_in,
                              void* d_out, int out_size) {
    int s = (in_sizes[0] <= 1) ? 0 : -1;
    const void*  ei        = d_in[1 + s];
    const float* edge_attr = (const float*)d_in[2 + s];
    const float* x         = (const float*)d_in[3 + s];
    const int*   node_mask = (const int*)d_in[4 + s];
    const float* mlp_w     = (const float*)d_in[5 + s];
    const float* w1        = (const float*)d_in[7 + s];
    const float* b1        = (const float*)d_in[8 + s];
    const float* w2        = (const float*)d_in[9 + s];
    const float* b2        = (const float*)d_in[10 + s];
    const float* fc_w      = (const float*)d_in[11 + s];
    const float* fc_b      = (const float*)d_in[12 + s];
    float*       out       = (float*)d_out;

    const int TB = 256;
    k_pre  <<<NE / TB, TB>>>(ei, edge_attr, x, mlp_w, w1);          // 512 blocks
    k_topk <<<N_NODES / 8, TB>>>(node_mask);                         // 512 blocks
    k_agg1 <<<NE / TB, TB>>>();                                      // 512 blocks (guarded)
    k_node2<<<(N_NODES * NH2) / TB, TB>>>(b1, w2);                   // 256 blocks
    k_agg2 <<<NE / TB, TB>>>();                                      // 512 blocks (guarded)
    k_out  <<<(N_NODES * NOUT) / TB, TB>>>(b2, fc_w, fc_b, out);     // 1792 blocks
}

// round 10
// speedup vs baseline: 2.4308x; 1.2818x over previous
#include <cuda_runtime.h>
#include <cuda_bf16.h>

#define N_NODES 4096
#define DIM     8
#define NE      131072
#define NH1     16
#define NH2     16
#define NOUT    112
#define TOPK    16
#define CAP     128
#define CAP_IN  96

// ---------------- scratch (zero-init at load; invariants restored per call) ----
__device__ float g_ev[NE];
__device__ int   g_row_cnt[N_NODES];          // zeroed by k_outg (end of call)
__device__ int   g_cols[N_NODES * CAP];
__device__ int   g_eids[N_NODES * CAP];
__device__ int   g_in_cnt[N_NODES];           // zeroed by k_pre (start of call)
__device__ int   g_in_list[N_NODES * CAP_IN]; // kept source rows per target
__device__ float g_xwnbr[N_NODES];
__device__ float g_hw1[N_NODES * NH1];
__device__ float g_hw2[N_NODES * NH2];

// ---------------- K1: probe + ev + scatter + xwnbr + hw1 + zero in_cnt -------
__global__ void k_pre(const void*  __restrict__ ei,
                      const float* __restrict__ edge_attr,
                      const float* __restrict__ x,
                      const float* __restrict__ mlp_w,
                      const float* __restrict__ w1) {
    __shared__ int s_is64;
    if (threadIdx.x < 32) {
        const int* raw = (const int*)ei;
        int nz = 0;
        for (int i = threadIdx.x; i < 1024; i += 32)
            if (raw[2 * i + 1] != 0) nz = 1;
        unsigned m = __ballot_sync(0xffffffffu, nz);
        if (threadIdx.x == 0) s_is64 = (m == 0) ? 1 : 0;
    }
    __syncthreads();
    const int is64 = s_is64;
    const int t = blockIdx.x * blockDim.x + threadIdx.x;

    if (t < NE) {
        const float4* ea = (const float4*)(edge_attr + t * DIM);
        float4 a0 = ea[0], a1 = ea[1];
        g_ev[t] = a0.x * mlp_w[16] + a0.y * mlp_w[17] + a0.z * mlp_w[18] + a0.w * mlp_w[19]
                + a1.x * mlp_w[20] + a1.y * mlp_w[21] + a1.z * mlp_w[22] + a1.w * mlp_w[23];
        int r, c;
        if (is64) {
            r = (int)((const long long*)ei)[t];
            c = (int)((const long long*)ei)[NE + t];
        } else {
            r = ((const int*)ei)[t];
            c = ((const int*)ei)[NE + t];
        }
        if ((unsigned)r < N_NODES && (unsigned)c < N_NODES) {
            int p = atomicAdd(&g_row_cnt[r], 1);
            if (p < CAP) {
                g_cols[r * CAP + p] = c;
                g_eids[r * CAP + p] = t;
            }
        }
    }
    if (t < N_NODES) {
        const float4* xr = (const float4*)(x + t * DIM);
        float4 x0 = xr[0], x1 = xr[1];
        g_xwnbr[t] = x0.x * mlp_w[8]  + x0.y * mlp_w[9]  + x0.z * mlp_w[10] + x0.w * mlp_w[11]
                   + x1.x * mlp_w[12] + x1.y * mlp_w[13] + x1.z * mlp_w[14] + x1.w * mlp_w[15];
        g_in_cnt[t] = 0;
    }
    if (t < N_NODES * NH1) {
        int n = t >> 4, j = t & 15;
        const float* xr = x + n * DIM;
        float s = 0.f;
#pragma unroll
        for (int d = 0; d < DIM; d++) s += xr[d] * w1[d * NH1 + j];
        g_hw1[t] = s;
    }
}

// ---------------- K2: top-K per row; emit into destination in-lists ----------
__global__ void k_topk(const int* __restrict__ node_mask) {
    __shared__ int           s_col[8][CAP];
    __shared__ int           s_eid[8][CAP];
    __shared__ float         s_key[8][CAP];
    __shared__ unsigned char s_rep[8][CAP];

    int w    = threadIdx.x >> 5;
    int lane = threadIdx.x & 31;
    int r    = blockIdx.x * 8 + w;
    if (r >= N_NODES) return;
    int base = r * CAP;
    int d = g_row_cnt[r]; if (d > CAP) d = CAP;

    for (int i = lane; i < d; i += 32) {
        s_col[w][i] = g_cols[base + i];
        s_eid[w][i] = g_eids[base + i];
    }
    __syncwarp();

    int myrep = 0;
    for (int i = lane; i < d; i += 32) {
        int ci = s_col[w][i];
        int ei_i = s_eid[w][i];
        int best = ei_i;
        for (int j = 0; j < d; j++)
            if (s_col[w][j] == ci && s_eid[w][j] > best) best = s_eid[w][j];
        unsigned char rp = (best == ei_i) ? 1 : 0;
        s_rep[w][i] = rp;
        s_key[w][i] = g_xwnbr[ci] + g_ev[best];
        myrep += rp;
    }
    __syncwarp();
    int nd = __reduce_add_sync(0xffffffffu, myrep);
    bool rowOK = (node_mask[r] != 0) && (nd >= TOPK);

    // all entries (duplicate edges of kept columns are each kept = per-edge w_e)
    if (rowOK) {
        for (int i = lane; i < d; i += 32) {
            float si = s_key[w][i];
            int   ci = s_col[w][i];
            int cnt = 0;
            for (int j = 0; j < d; j++) {
                if (s_rep[w][j]) {
                    float sj = s_key[w][j];
                    if (sj > si || (sj == si && s_col[w][j] < ci)) cnt++;
                }
            }
            if (cnt < TOPK) {
                int p = atomicAdd(&g_in_cnt[ci], 1);
                if (p < CAP_IN) g_in_list[ci * CAP_IN + p] = r;
            }
        }
    }
}

// ---------------- K3: gather layer1 + relu + @w2 -> hw2 ----------------------
// 16 nodes per block; thread (nn, j): gather feature j of node n
__global__ void k_layer1(const float* __restrict__ b1,
                         const float* __restrict__ w2) {
    __shared__ float s_h1[16][NH1 + 1];
    int nn = threadIdx.x >> 4;
    int j  = threadIdx.x & 15;
    int n  = blockIdx.x * 16 + nn;
    int cnt = g_in_cnt[n];
    int d = cnt < CAP_IN ? cnt : CAP_IN;
    int base = n * CAP_IN;
    float s = 0.f;
#pragma unroll 4
    for (int i = 0; i < d; i++) {
        int r = g_in_list[base + i];
        float dr = rsqrtf((float)g_in_cnt[r] + 1.0f);
        s += dr * g_hw1[r * NH1 + j];
    }
    float di = rsqrtf((float)cnt + 1.0f);
    float h = fmaxf(di * s + di * di * g_hw1[n * NH1 + j] + b1[j], 0.f);
    s_h1[nn][j] = h;
    __syncthreads();
    float o = 0.f;
#pragma unroll
    for (int k = 0; k < NH1; k++) o += s_h1[nn][k] * w2[k * NH2 + j];
    g_hw2[n * NH2 + j] = o;
}

// ---------------- K4: gather layer2 + relu + @fc -> out; cleanup -------------
// 2 nodes per block of 256; 128 threads per node
__global__ void k_outg(const float* __restrict__ b2,
                       const float* __restrict__ fc_w,
                       const float* __restrict__ fc_b,
                       float* __restrict__ out) {
    __shared__ float s_h2[2][NH2];
    int nn = threadIdx.x >> 7;
    int tt = threadIdx.x & 127;
    int n  = blockIdx.x * 2 + nn;

    if (tt < NH2) {
        int j = tt;
        int cnt = g_in_cnt[n];
        int d = cnt < CAP_IN ? cnt : CAP_IN;
        int base = n * CAP_IN;
        float s = 0.f;
#pragma unroll 4
        for (int i = 0; i < d; i++) {
            int r = g_in_list[base + i];
            float dr = rsqrtf((float)g_in_cnt[r] + 1.0f);
            s += dr * g_hw2[r * NH2 + j];
        }
        float di = rsqrtf((float)cnt + 1.0f);
        s_h2[nn][j] = fmaxf(di * s + di * di * g_hw2[n * NH2 + j] + b2[j], 0.f);
    }
    __syncthreads();
    if (tt < NOUT) {
        float s = fc_b[tt];
#pragma unroll
        for (int k = 0; k < NH2; k++) s += s_h2[nn][k] * fc_w[k * NOUT + tt];
        out[n * NOUT + tt] = s;
    }
    // cleanup for next call (row_cnt not read here)
    int g = blockIdx.x * blockDim.x + threadIdx.x;
    if (g < N_NODES) g_row_cnt[g] = 0;
}

// ---------------- launch ----------------
extern "C" void kernel_launch(void* const* d_in, const int* in_sizes, int n_in,
                              void* d_out, int out_size) {
    int s = (in_sizes[0] <= 1) ? 0 : -1;
    const void*  ei        = d_in[1 + s];
    const float* edge_attr = (const float*)d_in[2 + s];
    const float* x         = (const float*)d_in[3 + s];
    const int*   node_mask = (const int*)d_in[4 + s];
    const float* mlp_w     = (const float*)d_in[5 + s];
    const float* w1        = (const float*)d_in[7 + s];
    const float* b1        = (const float*)d_in[8 + s];
    const float* w2        = (const float*)d_in[9 + s];
    const float* b2        = (const float*)d_in[10 + s];
    const float* fc_w      = (const float*)d_in[11 + s];
    const float* fc_b      = (const float*)d_in[12 + s];
    float*       out       = (float*)d_out;

    const int TB = 256;
    k_pre   <<<NE / TB, TB>>>(ei, edge_attr, x, mlp_w, w1);   // 512 blocks
    k_topk  <<<N_NODES / 8, TB>>>(node_mask);                  // 512 blocks
    k_layer1<<<N_NODES / 16, TB>>>(b1, w2);                    // 256 blocks
    k_outg  <<<N_NODES / 2, TB>>>(b2, fc_w, fc_b, out);        // 2048 blocks
}